// round 10
// baseline (speedup 1.0000x reference)
#include <cuda_runtime.h>

// ---------------------------------------------------------------------------
// CrossViewSwapAttention — fp32, f32x2 FMA-bound design.
//   qf (L=64, Nq=384, d=128), kf/vf (L=64, Nk=480, d=128), heads 4 x dh 32.
// ---------------------------------------------------------------------------

#define NQ_ROWS  24576
#define NK_ROWS  30720
#define D        128

__device__ float g_qp [NQ_ROWS * D];
__device__ float g_kp [NK_ROWS * D];
__device__ float g_vp [NK_ROWS * D];
__device__ float g_att[NQ_ROWS * D];

typedef unsigned long long u64;

__device__ __forceinline__ u64 fma2(u64 a, u64 b, u64 c) {
    u64 d;
    asm("fma.rn.f32x2 %0, %1, %2, %3;" : "=l"(d) : "l"(a), "l"(b), "l"(c));
    return d;
}
__device__ __forceinline__ u64 add2(u64 a, u64 b) {
    u64 d;
    asm("add.rn.f32x2 %0, %1, %2;" : "=l"(d) : "l"(a), "l"(b));
    return d;
}
__device__ __forceinline__ u64 mul2(u64 a, u64 b) {
    u64 d;
    asm("mul.rn.f32x2 %0, %1, %2;" : "=l"(d) : "l"(a), "l"(b));
    return d;
}
__device__ __forceinline__ u64 pack2(float x, float y) {
    u64 d;
    asm("mov.b64 %0, {%1, %2};" : "=l"(d) : "f"(x), "f"(y));
    return d;
}
__device__ __forceinline__ float2 unpack2(u64 v) {
    float2 r;
    asm("mov.b64 {%0, %1}, %2;" : "=f"(r.x), "=f"(r.y) : "l"(v));
    return r;
}
__device__ __forceinline__ float ex2(float x) {
    float r;
    asm("ex2.approx.f32 %0, %1;" : "=f"(r) : "f"(x));
    return r;
}

// ---------------------------------------------------------------------------
// Kernel A: fused LayerNorm + Linear for q,k,v (one launch, 64 rows/block).
// Phase 2 streams W through a 16 KB SMEM quarter-buffer (4 refills) so the
// inner loop is all-SMEM. Dynamic smem = 50176 B.  (Unchanged from R9 win.)
// ---------------------------------------------------------------------------
#define LN_ROWS 64
#define XT_STRIDE 66
#define LN_SMEM_BYTES (128 * XT_STRIDE * 4 + 32 * 128 * 4)

__global__ __launch_bounds__(128, 4)
void ln_all_kernel(const float* __restrict__ q,
                   const float* __restrict__ k,
                   const float* __restrict__ v,
                   const float* __restrict__ lnq_g, const float* __restrict__ lnq_b,
                   const float* __restrict__ Wq,    const float* __restrict__ bq,
                   const float* __restrict__ lnk_g, const float* __restrict__ lnk_b,
                   const float* __restrict__ Wk,    const float* __restrict__ bk,
                   const float* __restrict__ lnv_g, const float* __restrict__ lnv_b,
                   const float* __restrict__ Wv,    const float* __restrict__ bv)
{
    extern __shared__ float smem[];
    float* xT  = smem;
    float* W_s = smem + 128 * XT_STRIDE;

    const int bx   = blockIdx.x;
    const int tid  = threadIdx.x;
    const int warp = tid >> 5;
    const int lane = tid & 31;

    const float *x, *gamma, *beta, *W, *blin;
    float* out;
    int rowsPerL, perN, rbase;
    if (bx < 384) {
        x = q; gamma = lnq_g; beta = lnq_b; W = Wq; blin = bq;
        out = g_qp; rowsPerL = 384; perN = 64; rbase = bx * LN_ROWS;
    } else if (bx < 864) {
        x = k; gamma = lnk_g; beta = lnk_b; W = Wk; blin = bk;
        out = g_kp; rowsPerL = 480; perN = 80; rbase = (bx - 384) * LN_ROWS;
    } else {
        x = v; gamma = lnv_g; beta = lnv_b; W = Wv; blin = bv;
        out = g_vp; rowsPerL = 480; perN = 80; rbase = (bx - 864) * LN_ROWS;
    }

    const float g0 = gamma[lane],      g1 = gamma[lane + 32],
                g2 = gamma[lane + 64], g3 = gamma[lane + 96];
    const float b0 = beta[lane],       b1 = beta[lane + 32],
                b2 = beta[lane + 64],  b3 = beta[lane + 96];

    #pragma unroll 4
    for (int rr = 0; rr < 16; rr++) {
        const int r   = warp * 16 + rr;
        const int row = rbase + r;
        const int L   = row / rowsPerL;
        const int N   = row - L * rowsPerL;
        const int nn  = N / perN;
        const int wi  = N - nn * perN;
        const float* xr = x + ((nn * 64 + L) * perN + wi) * D;

        const float v0 = xr[lane],      v1 = xr[lane + 32],
                    v2 = xr[lane + 64], v3 = xr[lane + 96];
        float s = v0 + v1 + v2 + v3;
        #pragma unroll
        for (int o = 16; o; o >>= 1) s += __shfl_xor_sync(0xffffffffu, s, o);
        const float mu = s * (1.0f / 128.0f);
        const float d0 = v0 - mu, d1 = v1 - mu, d2 = v2 - mu, d3 = v3 - mu;
        float sq = d0 * d0 + d1 * d1 + d2 * d2 + d3 * d3;
        #pragma unroll
        for (int o = 16; o; o >>= 1) sq += __shfl_xor_sync(0xffffffffu, sq, o);
        const float rstd = rsqrtf(sq * (1.0f / 128.0f) + 1e-5f);

        xT[(lane)      * XT_STRIDE + r] = d0 * rstd * g0 + b0;
        xT[(lane + 32) * XT_STRIDE + r] = d1 * rstd * g1 + b1;
        xT[(lane + 64) * XT_STRIDE + r] = d2 * rstd * g2 + b2;
        xT[(lane + 96) * XT_STRIDE + r] = d3 * rstd * g3 + b3;
    }

    const int rt = tid >> 4;
    const int c8 = (tid & 15) * 8;

    u64 acc2[4][8];
    #pragma unroll
    for (int c = 0; c < 8; c++) {
        const float bb = blin[c8 + c];
        const u64 bb2 = pack2(bb, bb);
        #pragma unroll
        for (int rp = 0; rp < 4; rp++) acc2[rp][c] = bb2;
    }

    const float* xrow = xT + rt * 8;

    for (int q4 = 0; q4 < 4; q4++) {
        __syncthreads();
        {
            const float4* src = (const float4*)(W + q4 * 32 * 128);
            float4* dst = (float4*)W_s;
            #pragma unroll
            for (int t = 0; t < 8; t++) dst[tid + t * 128] = src[tid + t * 128];
        }
        __syncthreads();

        #pragma unroll 4
        for (int jj = 0; jj < 32; jj++) {
            const int j = q4 * 32 + jj;
            const u64* xp = (const u64*)(xrow + j * XT_STRIDE);
            u64 xv[4];
            #pragma unroll
            for (int rp = 0; rp < 4; rp++) xv[rp] = xp[rp];

            const float4* wp = (const float4*)(W_s + jj * 128 + c8);
            const float4 wa = wp[0], wb = wp[1];
            u64 ws[8];
            ws[0] = pack2(wa.x, wa.x); ws[1] = pack2(wa.y, wa.y);
            ws[2] = pack2(wa.z, wa.z); ws[3] = pack2(wa.w, wa.w);
            ws[4] = pack2(wb.x, wb.x); ws[5] = pack2(wb.y, wb.y);
            ws[6] = pack2(wb.z, wb.z); ws[7] = pack2(wb.w, wb.w);

            #pragma unroll
            for (int rp = 0; rp < 4; rp++)
                #pragma unroll
                for (int c = 0; c < 8; c++)
                    acc2[rp][c] = fma2(xv[rp], ws[c], acc2[rp][c]);
        }
    }

    #pragma unroll
    for (int rp = 0; rp < 4; rp++) {
        float r0[8], r1[8];
        #pragma unroll
        for (int c = 0; c < 8; c++) {
            const float2 t = unpack2(acc2[rp][c]);
            r0[c] = t.x; r1[c] = t.y;
        }
        float* o0 = out + (rbase + rt * 8 + 2 * rp)     * D + c8;
        float* o1 = out + (rbase + rt * 8 + 2 * rp + 1) * D + c8;
        ((float4*)o0)[0] = make_float4(r0[0], r0[1], r0[2], r0[3]);
        ((float4*)o0)[1] = make_float4(r0[4], r0[5], r0[6], r0[7]);
        ((float4*)o1)[0] = make_float4(r1[0], r1[1], r1[2], r1[3]);
        ((float4*)o1)[1] = make_float4(r1[4], r1[5], r1[6], r1[7]);
    }
}

// ---------------------------------------------------------------------------
// Kernel B: attention — 1 q-row per thread, full dh in-thread, NO shuffles.
// Grid 768 = 4h * 64L * 3 q-tiles, 128 thr/block, 4 blocks/SM.
// Per key: 8 broadcast LDS.128 (K) + 16 fma2 into 4 partial trees + 3 add2
// + ex2 + 8 LDS.128 (V) + 16 fma2 PV.  q pre-scaled by coef*log2e.
// ---------------------------------------------------------------------------
#define KCHUNK 96

__global__ __launch_bounds__(128, 4)
void attn_kernel(const float* __restrict__ scale_ptr)
{
    __shared__ float4 ks4[KCHUNK * 8];
    __shared__ float4 vs4[KCHUNK * 8];

    const int bx  = blockIdx.x;
    const int h   = bx & 3;
    const int l   = (bx >> 2) & 63;
    const int qt  = bx >> 8;          // 0..2
    const int tid = threadIdx.x;
    const int qi  = qt * 128 + tid;

    const float coef = scale_ptr[0] * 0.17677669529663687f * 1.4426950408889634f;

    // q row (32 floats) pre-scaled into 16 f32x2 regs.
    u64 qr[16];
    {
        const float4* qp = (const float4*)(g_qp + (l * 384 + qi) * D + h * 32);
        #pragma unroll
        for (int i = 0; i < 8; i++) {
            const float4 t = qp[i];
            qr[2 * i]     = pack2(t.x * coef, t.y * coef);
            qr[2 * i + 1] = pack2(t.z * coef, t.w * coef);
        }
    }

    u64 acc[16];
    #pragma unroll
    for (int i = 0; i < 16; i++) acc[i] = 0ULL;
    float lsum = 0.0f;

    const float* kbase = g_kp + (l * 480) * D + h * 32;
    const float* vbase = g_vp + (l * 480) * D + h * 32;

    for (int c0 = 0; c0 < 480; c0 += KCHUNK) {
        __syncthreads();
        #pragma unroll
        for (int i = 0; i < (KCHUNK * 8) / 128; i++) {   // 6 iters
            const int idx = tid + i * 128;
            const int row = idx >> 3;
            const int c4  = idx & 7;
            ks4[idx] = *(const float4*)(kbase + (c0 + row) * D + c4 * 4);
            vs4[idx] = *(const float4*)(vbase + (c0 + row) * D + c4 * 4);
        }
        __syncthreads();

        #pragma unroll 4
        for (int kk = 0; kk < KCHUNK; kk++) {
            const u64* kr = (const u64*)(ks4 + kk * 8);
            // 4 partial f32x2 trees over the 16 dim-pairs (depth 4 each).
            u64 s0 = 0ULL, s1 = 0ULL, s2 = 0ULL, s3 = 0ULL;
            #pragma unroll
            for (int i = 0; i < 4; i++) {
                s0 = fma2(qr[i],      kr[i],      s0);
                s1 = fma2(qr[4 + i],  kr[4 + i],  s1);
                s2 = fma2(qr[8 + i],  kr[8 + i],  s2);
                s3 = fma2(qr[12 + i], kr[12 + i], s3);
            }
            const u64 sc = add2(add2(s0, s1), add2(s2, s3));
            const float2 t = unpack2(sc);
            const float p = ex2(t.x + t.y);
            lsum += p;
            const u64 p2 = pack2(p, p);

            const u64* vr = (const u64*)(vs4 + kk * 8);
            #pragma unroll
            for (int i = 0; i < 16; i++) acc[i] = fma2(p2, vr[i], acc[i]);
        }
    }

    const float inv = 1.0f / lsum;
    const u64 inv2 = pack2(inv, inv);
    u64* op = (u64*)(g_att + (l * 384 + qi) * D + h * 32);
    #pragma unroll
    for (int i = 0; i < 16; i++) op[i] = mul2(acc[i], inv2);
}

// ---------------------------------------------------------------------------
// Kernel C: mean over n (commutes with affine proj) + Wp + bp + skip.
// ---------------------------------------------------------------------------
__global__ __launch_bounds__(128)
void proj_kernel(const float* __restrict__ Wp,
                 const float* __restrict__ bp,
                 const float* __restrict__ skip,
                 float* __restrict__ out)
{
    __shared__ float ab[16][128];
    const int tid   = threadIdx.x;
    const int obase = blockIdx.x * 16;

    #pragma unroll
    for (int r = 0; r < 16; r++) {
        const int o  = obase + r;
        const int L  = o >> 6;
        const int wi = o & 63;
        float s = 0.0f;
        #pragma unroll
        for (int n = 0; n < 6; n++)
            s += g_att[(L * 384 + n * 64 + wi) * D + tid];
        ab[r][tid] = s * (1.0f / 6.0f);
    }
    __syncthreads();

    const int c = tid;
    float acc[16];
    const float bb = bp[c];
    #pragma unroll
    for (int r = 0; r < 16; r++) acc[r] = bb;

    #pragma unroll 4
    for (int j = 0; j < 128; j++) {
        const float w = Wp[j * 128 + c];
        #pragma unroll
        for (int r = 0; r < 16; r++) acc[r] = fmaf(ab[r][j], w, acc[r]);
    }
    #pragma unroll
    for (int r = 0; r < 16; r++) {
        const int o = obase + r;
        out[o * D + c] = acc[r] + skip[o * D + c];
    }
}

// ---------------------------------------------------------------------------
extern "C" void kernel_launch(void* const* d_in, const int* in_sizes, int n_in,
                              void* d_out, int out_size)
{
    const float* q          = (const float*)d_in[0];
    const float* k          = (const float*)d_in[1];
    const float* v          = (const float*)d_in[2];
    const float* skip       = (const float*)d_in[3];
    const float* attn_scale = (const float*)d_in[4];
    const float* lnq_g = (const float*)d_in[5];
    const float* lnq_b = (const float*)d_in[6];
    const float* Wq    = (const float*)d_in[7];
    const float* bq    = (const float*)d_in[8];
    const float* lnk_g = (const float*)d_in[9];
    const float* lnk_b = (const float*)d_in[10];
    const float* Wk    = (const float*)d_in[11];
    const float* bk    = (const float*)d_in[12];
    const float* lnv_g = (const float*)d_in[13];
    const float* lnv_b = (const float*)d_in[14];
    const float* Wv    = (const float*)d_in[15];
    const float* bv    = (const float*)d_in[16];
    const float* Wp    = (const float*)d_in[17];
    const float* bp    = (const float*)d_in[18];
    float* out = (float*)d_out;

    static int smem_set = 0;
    if (!smem_set) {
        cudaFuncSetAttribute(ln_all_kernel,
                             cudaFuncAttributeMaxDynamicSharedMemorySize,
                             LN_SMEM_BYTES);
        smem_set = 1;
    }

    ln_all_kernel<<<1344, 128, LN_SMEM_BYTES>>>(q, k, v,
                                                lnq_g, lnq_b, Wq, bq,
                                                lnk_g, lnk_b, Wk, bk,
                                                lnv_g, lnv_b, Wv, bv);

    attn_kernel<<<768, 128>>>(attn_scale);

    proj_kernel<<<4096 / 16, 128>>>(Wp, bp, skip, out);
}

// round 11
// speedup vs baseline: 2.1506x; 2.1506x over previous
#include <cuda_runtime.h>
#include <cuda_fp16.h>

// ---------------------------------------------------------------------------
// CrossViewSwapAttention — LN on fp32 f32x2 cores; attention on tensor cores
// (tf32 QK, fp16 PV, fp32 softmax).
//   qf (L=64, Nq=384, d=128), kf/vf (L=64, Nk=480, d=128), heads 4 x dh 32.
// ---------------------------------------------------------------------------

#define NQ_ROWS  24576
#define NK_ROWS  30720
#define D        128

__device__ float g_qp [NQ_ROWS * D];
__device__ float g_kp [NK_ROWS * D];
__device__ float g_vp [NK_ROWS * D];
__device__ float g_att[NQ_ROWS * D];

typedef unsigned long long u64;
typedef unsigned int u32;

__device__ __forceinline__ u64 fma2(u64 a, u64 b, u64 c) {
    u64 d;
    asm("fma.rn.f32x2 %0, %1, %2, %3;" : "=l"(d) : "l"(a), "l"(b), "l"(c));
    return d;
}
__device__ __forceinline__ u64 pack2(float x, float y) {
    u64 d;
    asm("mov.b64 %0, {%1, %2};" : "=l"(d) : "f"(x), "f"(y));
    return d;
}
__device__ __forceinline__ float2 unpack2(u64 v) {
    float2 r;
    asm("mov.b64 {%0, %1}, %2;" : "=f"(r.x), "=f"(r.y) : "l"(v));
    return r;
}
__device__ __forceinline__ float ex2(float x) {
    float r;
    asm("ex2.approx.f32 %0, %1;" : "=f"(r) : "f"(x));
    return r;
}
__device__ __forceinline__ u32 cvt_tf32(float x) {
    u32 r;
    asm("cvt.rna.tf32.f32 %0, %1;" : "=r"(r) : "f"(x));
    return r;
}
__device__ __forceinline__ void mma_tf32(float c[4], const u32 a[4], u32 b0, u32 b1) {
    asm("mma.sync.aligned.m16n8k8.row.col.f32.tf32.tf32.f32 "
        "{%0,%1,%2,%3}, {%4,%5,%6,%7}, {%8,%9}, {%0,%1,%2,%3};"
        : "+f"(c[0]), "+f"(c[1]), "+f"(c[2]), "+f"(c[3])
        : "r"(a[0]), "r"(a[1]), "r"(a[2]), "r"(a[3]), "r"(b0), "r"(b1));
}
__device__ __forceinline__ void mma_f16(float c[4], const u32 a[4], u32 b0, u32 b1) {
    asm("mma.sync.aligned.m16n8k16.row.col.f32.f16.f16.f32 "
        "{%0,%1,%2,%3}, {%4,%5,%6,%7}, {%8,%9}, {%0,%1,%2,%3};"
        : "+f"(c[0]), "+f"(c[1]), "+f"(c[2]), "+f"(c[3])
        : "r"(a[0]), "r"(a[1]), "r"(a[2]), "r"(a[3]), "r"(b0), "r"(b1));
}

// ---------------------------------------------------------------------------
// Kernel A: fused LayerNorm + Linear for q,k,v (unchanged from R9 win).
// ---------------------------------------------------------------------------
#define LN_ROWS 64
#define XT_STRIDE 66
#define LN_SMEM_BYTES (128 * XT_STRIDE * 4 + 32 * 128 * 4)

__global__ __launch_bounds__(128, 4)
void ln_all_kernel(const float* __restrict__ q,
                   const float* __restrict__ k,
                   const float* __restrict__ v,
                   const float* __restrict__ lnq_g, const float* __restrict__ lnq_b,
                   const float* __restrict__ Wq,    const float* __restrict__ bq,
                   const float* __restrict__ lnk_g, const float* __restrict__ lnk_b,
                   const float* __restrict__ Wk,    const float* __restrict__ bk,
                   const float* __restrict__ lnv_g, const float* __restrict__ lnv_b,
                   const float* __restrict__ Wv,    const float* __restrict__ bv)
{
    extern __shared__ float smem[];
    float* xT  = smem;
    float* W_s = smem + 128 * XT_STRIDE;

    const int bx   = blockIdx.x;
    const int tid  = threadIdx.x;
    const int warp = tid >> 5;
    const int lane = tid & 31;

    const float *x, *gamma, *beta, *W, *blin;
    float* out;
    int rowsPerL, perN, rbase;
    if (bx < 384) {
        x = q; gamma = lnq_g; beta = lnq_b; W = Wq; blin = bq;
        out = g_qp; rowsPerL = 384; perN = 64; rbase = bx * LN_ROWS;
    } else if (bx < 864) {
        x = k; gamma = lnk_g; beta = lnk_b; W = Wk; blin = bk;
        out = g_kp; rowsPerL = 480; perN = 80; rbase = (bx - 384) * LN_ROWS;
    } else {
        x = v; gamma = lnv_g; beta = lnv_b; W = Wv; blin = bv;
        out = g_vp; rowsPerL = 480; perN = 80; rbase = (bx - 864) * LN_ROWS;
    }

    const float g0 = gamma[lane],      g1 = gamma[lane + 32],
                g2 = gamma[lane + 64], g3 = gamma[lane + 96];
    const float b0 = beta[lane],       b1 = beta[lane + 32],
                b2 = beta[lane + 64],  b3 = beta[lane + 96];

    #pragma unroll 4
    for (int rr = 0; rr < 16; rr++) {
        const int r   = warp * 16 + rr;
        const int row = rbase + r;
        const int L   = row / rowsPerL;
        const int N   = row - L * rowsPerL;
        const int nn  = N / perN;
        const int wi  = N - nn * perN;
        const float* xr = x + ((nn * 64 + L) * perN + wi) * D;

        const float v0 = xr[lane],      v1 = xr[lane + 32],
                    v2 = xr[lane + 64], v3 = xr[lane + 96];
        float s = v0 + v1 + v2 + v3;
        #pragma unroll
        for (int o = 16; o; o >>= 1) s += __shfl_xor_sync(0xffffffffu, s, o);
        const float mu = s * (1.0f / 128.0f);
        const float d0 = v0 - mu, d1 = v1 - mu, d2 = v2 - mu, d3 = v3 - mu;
        float sq = d0 * d0 + d1 * d1 + d2 * d2 + d3 * d3;
        #pragma unroll
        for (int o = 16; o; o >>= 1) sq += __shfl_xor_sync(0xffffffffu, sq, o);
        const float rstd = rsqrtf(sq * (1.0f / 128.0f) + 1e-5f);

        xT[(lane)      * XT_STRIDE + r] = d0 * rstd * g0 + b0;
        xT[(lane + 32) * XT_STRIDE + r] = d1 * rstd * g1 + b1;
        xT[(lane + 64) * XT_STRIDE + r] = d2 * rstd * g2 + b2;
        xT[(lane + 96) * XT_STRIDE + r] = d3 * rstd * g3 + b3;
    }

    const int rt = tid >> 4;
    const int c8 = (tid & 15) * 8;

    u64 acc2[4][8];
    #pragma unroll
    for (int c = 0; c < 8; c++) {
        const float bb = blin[c8 + c];
        const u64 bb2 = pack2(bb, bb);
        #pragma unroll
        for (int rp = 0; rp < 4; rp++) acc2[rp][c] = bb2;
    }

    const float* xrow = xT + rt * 8;

    for (int q4 = 0; q4 < 4; q4++) {
        __syncthreads();
        {
            const float4* src = (const float4*)(W + q4 * 32 * 128);
            float4* dst = (float4*)W_s;
            #pragma unroll
            for (int t = 0; t < 8; t++) dst[tid + t * 128] = src[tid + t * 128];
        }
        __syncthreads();

        #pragma unroll 4
        for (int jj = 0; jj < 32; jj++) {
            const int j = q4 * 32 + jj;
            const u64* xp = (const u64*)(xrow + j * XT_STRIDE);
            u64 xv[4];
            #pragma unroll
            for (int rp = 0; rp < 4; rp++) xv[rp] = xp[rp];

            const float4* wp = (const float4*)(W_s + jj * 128 + c8);
            const float4 wa = wp[0], wb = wp[1];
            u64 ws[8];
            ws[0] = pack2(wa.x, wa.x); ws[1] = pack2(wa.y, wa.y);
            ws[2] = pack2(wa.z, wa.z); ws[3] = pack2(wa.w, wa.w);
            ws[4] = pack2(wb.x, wb.x); ws[5] = pack2(wb.y, wb.y);
            ws[6] = pack2(wb.z, wb.z); ws[7] = pack2(wb.w, wb.w);

            #pragma unroll
            for (int rp = 0; rp < 4; rp++)
                #pragma unroll
                for (int c = 0; c < 8; c++)
                    acc2[rp][c] = fma2(xv[rp], ws[c], acc2[rp][c]);
        }
    }

    #pragma unroll
    for (int rp = 0; rp < 4; rp++) {
        float r0[8], r1[8];
        #pragma unroll
        for (int c = 0; c < 8; c++) {
            const float2 t = unpack2(acc2[rp][c]);
            r0[c] = t.x; r1[c] = t.y;
        }
        float* o0 = out + (rbase + rt * 8 + 2 * rp)     * D + c8;
        float* o1 = out + (rbase + rt * 8 + 2 * rp + 1) * D + c8;
        ((float4*)o0)[0] = make_float4(r0[0], r0[1], r0[2], r0[3]);
        ((float4*)o0)[1] = make_float4(r0[4], r0[5], r0[6], r0[7]);
        ((float4*)o1)[0] = make_float4(r1[0], r1[1], r1[2], r1[3]);
        ((float4*)o1)[1] = make_float4(r1[4], r1[5], r1[6], r1[7]);
    }
}

// ---------------------------------------------------------------------------
// Kernel B: tensor-core flash attention.
// Block = (h, l, qt): 128 q-rows, 4 warps (warp owns 32 rows = 2 m16 tiles).
// 5 chunks of 96 keys. QK: mma tf32 m16n8k8 (K staged tf32-rounded, pad 36:
// B-frag bank = 4g+tig, conflict-free). Softmax: fp32 ex2 on C frags; P packed
// to fp16 A-frags IN REGISTERS (FA2 identity, no SMEM round trip).
// PV: mma fp16 m16n8k16, V staged fp16 TRANSPOSED (VT[dim][key], pad 104:
// conflict-free aligned half2 B-frags). Row sums quad-reduced at the end.
// ---------------------------------------------------------------------------
#define QS_STRIDE 33
#define KS_STRIDE 36
#define VT_STRIDE 104

__global__ __launch_bounds__(128, 4)
void attn_kernel(const float* __restrict__ scale_ptr)
{
    __shared__ float  Qs[128 * QS_STRIDE];   // 16896 B, tf32-rounded, pre-scaled
    __shared__ float  Ks[96 * KS_STRIDE];    // 13824 B, tf32-rounded
    __shared__ __half VT[32 * VT_STRIDE];    //  6656 B, [dim][key] fp16

    const int bx   = blockIdx.x;
    const int h    = bx & 3;
    const int l    = (bx >> 2) & 63;
    const int qt   = bx >> 8;            // 0..2
    const int tid  = threadIdx.x;
    const int w    = tid >> 5;
    const int lane = tid & 31;
    const int g    = lane >> 2;          // 0..7
    const int tig  = lane & 3;           // 0..3

    const float coef = scale_ptr[0] * 0.17677669529663687f * 1.4426950408889634f;

    const float* qbase = g_qp + (l * 384 + qt * 128) * D + h * 32;
    const float* kbase = g_kp + (l * 480) * D + h * 32;
    const float* vbase = g_vp + (l * 480) * D + h * 32;

    // ---- Stage Q once (128 rows x 32 dims), scaled + tf32-rounded ----
    #pragma unroll
    for (int t = 0; t < 8; t++) {
        const int idx = tid + t * 128;
        const int row = idx >> 3;
        const int c4  = idx & 7;
        const float4 f = *(const float4*)(qbase + row * D + c4 * 4);
        float* d = Qs + row * QS_STRIDE + c4 * 4;
        d[0] = __uint_as_float(cvt_tf32(f.x * coef));
        d[1] = __uint_as_float(cvt_tf32(f.y * coef));
        d[2] = __uint_as_float(cvt_tf32(f.z * coef));
        d[3] = __uint_as_float(cvt_tf32(f.w * coef));
    }
    __syncthreads();

    // ---- Q A-fragments (2 m16 tiles x 4 k-steps), held for whole kernel ----
    u32 qa[2][4][4];
    #pragma unroll
    for (int mt = 0; mt < 2; mt++) {
        const int r0 = w * 32 + mt * 16;
        #pragma unroll
        for (int ks = 0; ks < 4; ks++) {
            qa[mt][ks][0] = __float_as_uint(Qs[(r0 + g)     * QS_STRIDE + ks * 8 + tig]);
            qa[mt][ks][1] = __float_as_uint(Qs[(r0 + g + 8) * QS_STRIDE + ks * 8 + tig]);
            qa[mt][ks][2] = __float_as_uint(Qs[(r0 + g)     * QS_STRIDE + ks * 8 + tig + 4]);
            qa[mt][ks][3] = __float_as_uint(Qs[(r0 + g + 8) * QS_STRIDE + ks * 8 + tig + 4]);
        }
    }

    float o[2][4][4];   // [mt][dim n8-tile][C frag]
    #pragma unroll
    for (int mt = 0; mt < 2; mt++)
        #pragma unroll
        for (int vn = 0; vn < 4; vn++)
            #pragma unroll
            for (int i = 0; i < 4; i++) o[mt][vn][i] = 0.0f;
    float rs0[2] = {0.f, 0.f};   // row g sums per mt
    float rs1[2] = {0.f, 0.f};   // row g+8 sums per mt

    for (int c0 = 0; c0 < 480; c0 += 96) {
        __syncthreads();
        // ---- Stage K (tf32-rounded) and V (fp16 transposed) ----
        #pragma unroll
        for (int t = 0; t < 6; t++) {
            const int idx = tid + t * 128;
            const int row = idx >> 3;
            const int c4  = idx & 7;
            const float4 fk = *(const float4*)(kbase + (c0 + row) * D + c4 * 4);
            float* dk = Ks + row * KS_STRIDE + c4 * 4;
            dk[0] = __uint_as_float(cvt_tf32(fk.x));
            dk[1] = __uint_as_float(cvt_tf32(fk.y));
            dk[2] = __uint_as_float(cvt_tf32(fk.z));
            dk[3] = __uint_as_float(cvt_tf32(fk.w));
            const float4 fv = *(const float4*)(vbase + (c0 + row) * D + c4 * 4);
            VT[(c4 * 4 + 0) * VT_STRIDE + row] = __float2half_rn(fv.x);
            VT[(c4 * 4 + 1) * VT_STRIDE + row] = __float2half_rn(fv.y);
            VT[(c4 * 4 + 2) * VT_STRIDE + row] = __float2half_rn(fv.z);
            VT[(c4 * 4 + 3) * VT_STRIDE + row] = __float2half_rn(fv.w);
        }
        __syncthreads();

        // ---- 6 pairs of n8 tiles (16 keys each) ----
        #pragma unroll
        for (int pt = 0; pt < 6; pt++) {
            float s[2][2][4];
            #pragma unroll
            for (int mt = 0; mt < 2; mt++)
                #pragma unroll
                for (int n2 = 0; n2 < 2; n2++)
                    #pragma unroll
                    for (int i = 0; i < 4; i++) s[mt][n2][i] = 0.0f;

            #pragma unroll
            for (int n2 = 0; n2 < 2; n2++) {
                const int n0 = pt * 16 + n2 * 8;
                #pragma unroll
                for (int ks = 0; ks < 4; ks++) {
                    const u32 b0 = __float_as_uint(Ks[(n0 + g) * KS_STRIDE + ks * 8 + tig]);
                    const u32 b1 = __float_as_uint(Ks[(n0 + g) * KS_STRIDE + ks * 8 + tig + 4]);
                    mma_tf32(s[0][n2], qa[0][ks], b0, b1);
                    mma_tf32(s[1][n2], qa[1][ks], b0, b1);
                }
            }

            // exp + row-sum + pack into fp16 A-frags (FA2 identity)
            u32 aP[2][4];
            #pragma unroll
            for (int mt = 0; mt < 2; mt++) {
                #pragma unroll
                for (int n2 = 0; n2 < 2; n2++) {
                    const float p0 = ex2(s[mt][n2][0]);
                    const float p1 = ex2(s[mt][n2][1]);
                    const float p2 = ex2(s[mt][n2][2]);
                    const float p3 = ex2(s[mt][n2][3]);
                    rs0[mt] += p0 + p1;
                    rs1[mt] += p2 + p3;
                    const __half2 h01 = __floats2half2_rn(p0, p1);
                    const __half2 h23 = __floats2half2_rn(p2, p3);
                    aP[mt][n2 * 2 + 0] = *(const u32*)&h01;  // a0 / a2
                    aP[mt][n2 * 2 + 1] = *(const u32*)&h23;  // a1 / a3
                }
                // reorder: a = {n2=0:(c0c1), n2=0:(c2c3), n2=1:(c0c1), n2=1:(c2c3)}
                // already in slots {0,1,2,3} = {a0,a1,a2,a3}  ✓
            }

            // PV: one k16 step (keys pt*16..+16) x 4 dim-tiles
            #pragma unroll
            for (int vn = 0; vn < 4; vn++) {
                const __half* vb = VT + (vn * 8 + g) * VT_STRIDE + pt * 16 + 2 * tig;
                const u32 b0 = *(const u32*)(vb);
                const u32 b1 = *(const u32*)(vb + 8);
                mma_f16(o[0][vn], aP[0], b0, b1);
                mma_f16(o[1][vn], aP[1], b0, b1);
            }
        }
    }

    // ---- Normalize and write ----
    #pragma unroll
    for (int mt = 0; mt < 2; mt++) {
        float s0 = rs0[mt];
        s0 += __shfl_xor_sync(0xffffffffu, s0, 1);
        s0 += __shfl_xor_sync(0xffffffffu, s0, 2);
        float s1 = rs1[mt];
        s1 += __shfl_xor_sync(0xffffffffu, s1, 1);
        s1 += __shfl_xor_sync(0xffffffffu, s1, 2);
        const float inv0 = 1.0f / s0;
        const float inv1 = 1.0f / s1;

        const int r0 = qt * 128 + w * 32 + mt * 16 + g;
        #pragma unroll
        for (int vn = 0; vn < 4; vn++) {
            float* p0 = g_att + (l * 384 + r0)     * D + h * 32 + vn * 8 + 2 * tig;
            float* p1 = g_att + (l * 384 + r0 + 8) * D + h * 32 + vn * 8 + 2 * tig;
            *(u64*)p0 = pack2(o[mt][vn][0] * inv0, o[mt][vn][1] * inv0);
            *(u64*)p1 = pack2(o[mt][vn][2] * inv1, o[mt][vn][3] * inv1);
        }
    }
}

// ---------------------------------------------------------------------------
// Kernel C: mean over n (commutes with affine proj) + Wp + bp + skip.
// ---------------------------------------------------------------------------
__global__ __launch_bounds__(128)
void proj_kernel(const float* __restrict__ Wp,
                 const float* __restrict__ bp,
                 const float* __restrict__ skip,
                 float* __restrict__ out)
{
    __shared__ float ab[16][128];
    const int tid   = threadIdx.x;
    const int obase = blockIdx.x * 16;

    #pragma unroll
    for (int r = 0; r < 16; r++) {
        const int o  = obase + r;
        const int L  = o >> 6;
        const int wi = o & 63;
        float s = 0.0f;
        #pragma unroll
        for (int n = 0; n < 6; n++)
            s += g_att[(L * 384 + n * 64 + wi) * D + tid];
        ab[r][tid] = s * (1.0f / 6.0f);
    }
    __syncthreads();

    const int c = tid;
    float acc[16];
    const float bb = bp[c];
    #pragma unroll
    for (int r = 0; r < 16; r++) acc[r] = bb;

    #pragma unroll 4
    for (int j = 0; j < 128; j++) {
        const float w = Wp[j * 128 + c];
        #pragma unroll
        for (int r = 0; r < 16; r++) acc[r] = fmaf(ab[r][j], w, acc[r]);
    }
    #pragma unroll
    for (int r = 0; r < 16; r++) {
        const int o = obase + r;
        out[o * D + c] = acc[r] + skip[o * D + c];
    }
}

// ---------------------------------------------------------------------------
extern "C" void kernel_launch(void* const* d_in, const int* in_sizes, int n_in,
                              void* d_out, int out_size)
{
    const float* q          = (const float*)d_in[0];
    const float* k          = (const float*)d_in[1];
    const float* v          = (const float*)d_in[2];
    const float* skip       = (const float*)d_in[3];
    const float* attn_scale = (const float*)d_in[4];
    const float* lnq_g = (const float*)d_in[5];
    const float* lnq_b = (const float*)d_in[6];
    const float* Wq    = (const float*)d_in[7];
    const float* bq    = (const float*)d_in[8];
    const float* lnk_g = (const float*)d_in[9];
    const float* lnk_b = (const float*)d_in[10];
    const float* Wk    = (const float*)d_in[11];
    const float* bk    = (const float*)d_in[12];
    const float* lnv_g = (const float*)d_in[13];
    const float* lnv_b = (const float*)d_in[14];
    const float* Wv    = (const float*)d_in[15];
    const float* bv    = (const float*)d_in[16];
    const float* Wp    = (const float*)d_in[17];
    const float* bp    = (const float*)d_in[18];
    float* out = (float*)d_out;

    static int smem_set = 0;
    if (!smem_set) {
        cudaFuncSetAttribute(ln_all_kernel,
                             cudaFuncAttributeMaxDynamicSharedMemorySize,
                             LN_SMEM_BYTES);
        smem_set = 1;
    }

    ln_all_kernel<<<1344, 128, LN_SMEM_BYTES>>>(q, k, v,
                                                lnq_g, lnq_b, Wq, bq,
                                                lnk_g, lnk_b, Wk, bk,
                                                lnv_g, lnv_b, Wv, bv);

    // 4 heads * 64 L * 3 q-tiles of 128 rows
    attn_kernel<<<768, 128>>>(attn_scale);

    proj_kernel<<<4096 / 16, 128>>>(Wp, bp, skip, out);
}